// round 3
// baseline (speedup 1.0000x reference)
#include <cuda_runtime.h>

#define NCLS 19
#define FPX  16384      // 128*128 feature pixels
#define DCH  64
#define LBL  512
#define NT   256
#define CSTRIDE 20      // padded class stride for per-pixel counts

__device__ unsigned char g_cnt8[FPX * CSTRIDE];
__device__ unsigned int  g_pairs[NCLS * FPX];   // (w<<16)|pixel, pixel-ordered
__device__ int           g_len[NCLS];
__device__ float         g_loss[NCLS * DCH];
__device__ float         g_n[NCLS];

__device__ __forceinline__ float ex2f(float x) {
    float y;
    asm("ex2.approx.ftz.f32 %0, %1;" : "=f"(y) : "f"(x));
    return y;
}

// K1a: per-(feature-pixel, class) counts. One warp handles one feature pixel:
// all 32 lanes load the same 16 labels (broadcast), lane == class id.
__global__ void count_kernel(const int* __restrict__ label) {
    int fp   = blockIdx.x * 8 + threadIdx.y;
    int lane = threadIdx.x;
    int r = fp >> 7, c = fp & 127;
    int cnt = 0;
#pragma unroll
    for (int dr = 0; dr < 4; dr++) {
        int4 v = *reinterpret_cast<const int4*>(label + (4 * r + dr) * LBL + 4 * c);
        cnt += (v.x == lane) + (v.y == lane) + (v.z == lane) + (v.w == lane);
    }
    if (lane < NCLS) g_cnt8[fp * CSTRIDE + lane] = (unsigned char)cnt;
}

// K1b: deterministic ordered compaction: one block per class, ballot + block scan.
__global__ __launch_bounds__(NT) void compact_kernel() {
    const int cls  = blockIdx.x;
    const int tid  = threadIdx.x;
    const int lane = tid & 31, wid = tid >> 5;
    __shared__ unsigned int wsum[8];
    __shared__ unsigned int sbase;
    if (tid == 0) sbase = 0;
    __syncthreads();

    unsigned int* __restrict__ out = g_pairs + cls * FPX;

    for (int c0 = 0; c0 < FPX; c0 += NT) {
        int fp = c0 + tid;
        unsigned int w = g_cnt8[fp * CSTRIDE + cls];
        unsigned int mask = __ballot_sync(0xffffffffu, w > 0);
        if (lane == 0) wsum[wid] = __popc(mask);
        __syncthreads();
        unsigned int off = sbase;
#pragma unroll
        for (int j = 0; j < 8; j++) off += (j < wid) ? wsum[j] : 0u;
        off += __popc(mask & ((1u << lane) - 1u));
        if (w > 0) out[off] = (w << 16) | (unsigned int)fp;
        __syncthreads();
        if (tid == 0) {
            unsigned int tot = 0;
#pragma unroll
            for (int j = 0; j < 8; j++) tot += wsum[j];
            sbase += tot;
        }
        __syncthreads();
    }
    if (tid == 0) g_len[cls] = (int)sbase;
}

// K2: one block per (class, channel). Compacted moments + weighted 7-bin KDE.
__global__ __launch_bounds__(NT) void klass_kernel(const float* __restrict__ feat) {
    const int cls = blockIdx.x;
    const int dd  = blockIdx.y;
    const float* __restrict__ fb = feat + dd * FPX;
    const unsigned int* __restrict__ pr = g_pairs + cls * FPX;
    const int len = g_len[cls];
    const int tid  = threadIdx.x;
    const int lane = tid & 31, wid = tid >> 5;

    __shared__ float red[10][8];

    // ---- phase 1: n, sum(w*f), sum(w*f^2) over nonzero pixels ----
    float s0 = 0.f, s1 = 0.f, s2 = 0.f;
    for (int i = tid; i < len; i += NT) {
        unsigned int p = pr[i];
        float w = (float)(p >> 16);
        float f = fb[p & 0xFFFFu];
        s0 += w;
        s1 = fmaf(w, f, s1);
        s2 = fmaf(w * f, f, s2);
    }
#pragma unroll
    for (int o = 16; o; o >>= 1) {
        s0 += __shfl_xor_sync(0xffffffffu, s0, o);
        s1 += __shfl_xor_sync(0xffffffffu, s1, o);
        s2 += __shfl_xor_sync(0xffffffffu, s2, o);
    }
    if (lane == 0) { red[0][wid] = s0; red[1][wid] = s1; red[2][wid] = s2; }
    __syncthreads();
    float n = 0.f, S1 = 0.f, S2 = 0.f;
#pragma unroll
    for (int j = 0; j < 8; j++) { n += red[0][j]; S1 += red[1][j]; S2 += red[2][j]; }

    float nsafe = fmaxf(n, 1.0f);
    float miu   = S1 / nsafe;
    float var   = fmaxf(S2 / nsafe - miu * miu, 0.0f) + 1e-10f;
    float inv5  = 5.0f * rsqrtf(var);        // 5/std
    float nm5   = -miu * inv5;

    // ---- phase 2: 7-bin weighted KDE ----
    // arg_k = C2*(u-k5)^2 = fma(-2*k5, q, r + C2*k5^2), q = C2*u, r = C2*u^2
    const float C2 = -0.72134752f;            // -0.5 * log2(e)
    float acc[7] = {0.f, 0.f, 0.f, 0.f, 0.f, 0.f, 0.f};

    for (int i = tid; i < len; i += NT) {
        unsigned int p = pr[i];
        float w = (float)(p >> 16);
        float f = fb[p & 0xFFFFu];
        float u = fmaf(f, inv5, nm5);
        float q = C2 * u;
        float r = q * u;
#pragma unroll
        for (int k = 0; k < 7; k++) {
            const float k5 = (float)(5 * (k - 3));
            float arg = fmaf(-2.0f * k5, q, r + C2 * k5 * k5);
            acc[k] = fmaf(w, ex2f(arg), acc[k]);
        }
    }

#pragma unroll
    for (int k = 0; k < 7; k++) {
        float v = acc[k];
#pragma unroll
        for (int o = 16; o; o >>= 1) v += __shfl_xor_sync(0xffffffffu, v, o);
        if (lane == 0) red[3 + k][wid] = v;
    }
    __syncthreads();

    if (tid == 0) {
        float s[7], tot = 0.f;
#pragma unroll
        for (int k = 0; k < 7; k++) {
            float v = 0.f;
#pragma unroll
            for (int j = 0; j < 8; j++) v += red[3 + k][j];
            s[k] = v; tot += v;
        }
        float inv = 1.0f / fmaxf(tot, 1e-30f);
        const float targ[7] = {0.00443305f, 0.05400558f, 0.24203623f, 0.39905027f,
                               0.24203623f, 0.05400558f, 0.00443305f};
        float L = 0.f;
#pragma unroll
        for (int k = 0; k < 7; k++) {
            float dif = fabsf(s[k] * inv - targ[k]);
            L += (dif < 1.0f) ? 0.5f * dif * dif : (dif - 0.5f);
        }
        float active = (n >= 1000.0f) ? 1.0f : 0.0f;
        g_loss[cls * DCH + dd] = active * L * (1.0f / (7.0f * (float)DCH));
        if (dd == 0) g_n[cls] = n;
    }
}

// K3: final deterministic reduction -> scalar loss
__global__ void final_kernel(float* __restrict__ out) {
    const int tid  = threadIdx.x;
    const int lane = tid & 31, wid = tid >> 5;
    __shared__ float red[8];
    float s = 0.f;
    for (int i = tid; i < NCLS * DCH; i += NT) s += g_loss[i];
#pragma unroll
    for (int o = 16; o; o >>= 1) s += __shfl_xor_sync(0xffffffffu, s, o);
    if (lane == 0) red[wid] = s;
    __syncthreads();
    if (tid == 0) {
        float num = 0.f;
#pragma unroll
        for (int j = 0; j < 8; j++) num += red[j];
        float den = 0.f;
        for (int c = 0; c < NCLS; c++) den += (g_n[c] >= 1000.0f) ? 1.0f : 0.0f;
        out[0] = num / den;
    }
}

extern "C" void kernel_launch(void* const* d_in, const int* in_sizes, int n_in,
                              void* d_out, int out_size) {
    const float* feature;
    const int*   label;
    if (in_sizes[0] == DCH * FPX) {
        feature = (const float*)d_in[0];
        label   = (const int*)d_in[1];
    } else {
        feature = (const float*)d_in[1];
        label   = (const int*)d_in[0];
    }
    count_kernel<<<FPX / 8, dim3(32, 8)>>>(label);
    compact_kernel<<<NCLS, NT>>>();
    klass_kernel<<<dim3(NCLS, DCH), NT>>>(feature);
    final_kernel<<<1, NT>>>((float*)d_out);
}

// round 5
// speedup vs baseline: 1.2778x; 1.2778x over previous
#include <cuda_runtime.h>

#define NCLS 19
#define FPX  16384      // 128*128 feature pixels
#define DCH  64
#define LBL  512
#define NTA  256        // count/compact block size
#define NTK  128        // klass block size
#define PADQ 512        // pad quantum (multiple of 4*NTK)

__device__ unsigned int g_pairs[NCLS * FPX];   // (w<<16)|pixel, pixel-ordered, zero-padded
__device__ int          g_len[NCLS];           // padded length
__device__ float        g_n[NCLS];
__device__ float        g_loss[NCLS * DCH];
__device__ unsigned int g_ticket;

typedef unsigned long long ull;

__device__ __forceinline__ float ex2f(float x) {
    float y; asm("ex2.approx.ftz.f32 %0, %1;" : "=f"(y) : "f"(x)); return y;
}
__device__ __forceinline__ ull pk2(float lo, float hi) {
    ull r; asm("mov.b64 %0, {%1, %2};" : "=l"(r) : "f"(lo), "f"(hi)); return r;
}
__device__ __forceinline__ void upk2(float& lo, float& hi, ull v) {
    asm("mov.b64 {%0, %1}, %2;" : "=f"(lo), "=f"(hi) : "l"(v));
}
__device__ __forceinline__ ull fma2(ull a, ull b, ull c) {
    ull d; asm("fma.rn.f32x2 %0, %1, %2, %3;" : "=l"(d) : "l"(a), "l"(b), "l"(c)); return d;
}
__device__ __forceinline__ ull add2(ull a, ull b) {
    ull d; asm("add.rn.f32x2 %0, %1, %2;" : "=l"(d) : "l"(a), "l"(b)); return d;
}
__device__ __forceinline__ ull mul2(ull a, ull b) {
    ull d; asm("mul.rn.f32x2 %0, %1, %2;" : "=l"(d) : "l"(a), "l"(b)); return d;
}

// K1: fused count + ordered compaction. One block per class.
__global__ __launch_bounds__(NTA) void count_compact_kernel(const int* __restrict__ label) {
    const int cls = blockIdx.x;
    const int tid = threadIdx.x, lane = tid & 31, wid = tid >> 5;
    __shared__ unsigned char sw[FPX];          // per-pixel weight for this class
    __shared__ unsigned int  wtot[8], wbase[8];
    __shared__ int           wsumw[8];
    __shared__ unsigned int  stot;

    // phase A: coalesced label reads, per-pixel 4x4 count
#pragma unroll 4
    for (int i = 0; i < 64; i++) {
        int fp = i * NTA + tid;
        int r = fp >> 7, c = fp & 127;
        const int4* lp = reinterpret_cast<const int4*>(label + (r * 4) * LBL + c * 4);
        int cnt = 0;
#pragma unroll
        for (int dr = 0; dr < 4; dr++) {
            int4 v = lp[dr * (LBL / 4)];
            cnt += (v.x == cls) + (v.y == cls) + (v.z == cls) + (v.w == cls);
        }
        sw[fp] = (unsigned char)cnt;
    }
    __syncthreads();

    // phase B: single block scan over per-thread (64 contiguous pixels) nnz
    const int base = tid * 64;
    int nnz = 0, ws = 0;
#pragma unroll
    for (int j = 0; j < 64; j += 4) {
        unsigned u = *reinterpret_cast<const unsigned*>(sw + base + j);
        nnz += __popc(__vcmpne4(u, 0u) & 0x01010101u);
        ws  += (u & 0xff) + ((u >> 8) & 0xff) + ((u >> 16) & 0xff) + (u >> 24);
    }
    unsigned inc = (unsigned)nnz;
#pragma unroll
    for (int o = 1; o < 32; o <<= 1) {
        unsigned t = __shfl_up_sync(0xffffffffu, inc, o);
        if (lane >= o) inc += t;
    }
    if (lane == 31) wtot[wid] = inc;
    int wsr = ws;
#pragma unroll
    for (int o = 16; o; o >>= 1) wsr += __shfl_xor_sync(0xffffffffu, wsr, o);
    if (lane == 0) wsumw[wid] = wsr;
    __syncthreads();
    if (tid == 0) {
        unsigned run = 0;
        int nsum = 0;
#pragma unroll
        for (int j = 0; j < 8; j++) { wbase[j] = run; run += wtot[j]; nsum += wsumw[j]; }
        stot = run;
        g_n[cls] = (float)nsum;
    }
    __syncthreads();

    unsigned rank = wbase[wid] + inc - (unsigned)nnz;
    unsigned int* __restrict__ out = g_pairs + cls * FPX;
    for (int j = 0; j < 64; j++) {
        unsigned w = sw[base + j];
        if (w) out[rank++] = (w << 16) | (unsigned)(base + j);
    }
    unsigned total = stot;
    unsigned pl = (total + PADQ - 1) & ~(unsigned)(PADQ - 1);
    for (unsigned k = total + tid; k < pl; k += NTA) out[k] = 0u;
    if (tid == 0) g_len[cls] = (int)pl;
}

// K2: one block per (class, channel). Compacted moments + packed-f32x2 7-bin KDE.
// Last block performs the final scalar reduction (ticket pattern).
__global__ __launch_bounds__(NTK) void klass_kernel(const float* __restrict__ feat,
                                                    float* __restrict__ outp) {
    const int cls = blockIdx.x, dd = blockIdx.y;
    const float* __restrict__ fb = feat + dd * FPX;
    const unsigned int* __restrict__ pr = g_pairs + cls * FPX;
    const int len = g_len[cls];
    const float n = g_n[cls];
    const int tid = threadIdx.x, lane = tid & 31, wid = tid >> 5;

    __shared__ float red[10][4];
    __shared__ bool  amlast;

    float loss = 0.f;
    if (n >= 1000.0f) {
        // ---- pass 1: moments ----
        float s0 = 0.f, s1 = 0.f, s2 = 0.f;
        for (int i = tid; i < len; i += NTK) {
            unsigned p = pr[i];
            float w = (float)(p >> 16);
            float f = fb[p & 0xFFFFu];
            s0 += w;
            s1 = fmaf(w, f, s1);
            s2 = fmaf(w * f, f, s2);
        }
#pragma unroll
        for (int o = 16; o; o >>= 1) {
            s0 += __shfl_xor_sync(0xffffffffu, s0, o);
            s1 += __shfl_xor_sync(0xffffffffu, s1, o);
            s2 += __shfl_xor_sync(0xffffffffu, s2, o);
        }
        if (lane == 0) { red[0][wid] = s0; red[1][wid] = s1; red[2][wid] = s2; }
        __syncthreads();
        float S0 = 0.f, S1 = 0.f, S2 = 0.f;
#pragma unroll
        for (int j = 0; j < 4; j++) { S0 += red[0][j]; S1 += red[1][j]; S2 += red[2][j]; }

        float nsafe = fmaxf(S0, 1.0f);
        float miu   = S1 / nsafe;
        float var   = fmaxf(S2 / nsafe - miu * miu, 0.0f) + 1e-10f;
        float inv5  = 5.0f * rsqrtf(var);
        float nm5   = -miu * inv5;

        // ---- pass 2: packed 7-bin KDE ----
        const float C2 = -0.72134752f;            // -0.5 * log2(e)
        ull inv5_2 = pk2(inv5, inv5);
        ull nm5_2  = pk2(nm5, nm5);
        ull C2_2   = pk2(C2, C2);
        ull ck2[7], mk2[7];
#pragma unroll
        for (int k = 0; k < 7; k++) {
            float k5 = (float)(5 * (k - 3));
            float ck = C2 * k5 * k5;
            float mk = -2.0f * k5;
            ck2[k] = pk2(ck, ck);
            mk2[k] = pk2(mk, mk);
        }
        ull acc[7];
#pragma unroll
        for (int k = 0; k < 7; k++) acc[k] = pk2(0.f, 0.f);

        for (int i = tid; i < len; i += 2 * NTK) {
            unsigned pa = pr[i], pb = pr[i + NTK];
            float fa = fb[pa & 0xFFFFu];
            float fc = fb[pb & 0xFFFFu];
            ull f2 = pk2(fa, fc);
            ull w2 = pk2((float)(pa >> 16), (float)(pb >> 16));
            ull u2 = fma2(f2, inv5_2, nm5_2);
            ull q2 = mul2(u2, C2_2);
            ull r2 = mul2(q2, u2);
#pragma unroll
            for (int k = 0; k < 7; k++) {
                ull t2 = add2(r2, ck2[k]);
                ull a2 = fma2(mk2[k], q2, t2);
                float lo, hi; upk2(lo, hi, a2);
                ull e2 = pk2(ex2f(lo), ex2f(hi));
                acc[k] = fma2(w2, e2, acc[k]);
            }
        }

#pragma unroll
        for (int k = 0; k < 7; k++) {
            float lo, hi; upk2(lo, hi, acc[k]);
            float v = lo + hi;
#pragma unroll
            for (int o = 16; o; o >>= 1) v += __shfl_xor_sync(0xffffffffu, v, o);
            if (lane == 0) red[3 + k][wid] = v;
        }
        __syncthreads();

        if (tid == 0) {
            float s[7], tot = 0.f;
#pragma unroll
            for (int k = 0; k < 7; k++) {
                float v = red[3 + k][0] + red[3 + k][1] + red[3 + k][2] + red[3 + k][3];
                s[k] = v; tot += v;
            }
            float inv = 1.0f / fmaxf(tot, 1e-30f);
            const float targ[7] = {0.00443305f, 0.05400558f, 0.24203623f, 0.39905027f,
                                   0.24203623f, 0.05400558f, 0.00443305f};
            float L = 0.f;
#pragma unroll
            for (int k = 0; k < 7; k++) {
                float dif = fabsf(s[k] * inv - targ[k]);
                L += (dif < 1.0f) ? 0.5f * dif * dif : (dif - 0.5f);
            }
            loss = L * (1.0f / (7.0f * (float)DCH));
        }
    }
    if (tid == 0) g_loss[cls * DCH + dd] = loss;
    __threadfence();
    if (tid == 0) {
        unsigned t = atomicAdd(&g_ticket, 1u);
        amlast = (t == (unsigned)(NCLS * DCH - 1));
    }
    __syncthreads();

    if (amlast) {
        __threadfence();
        float s = 0.f;
        for (int i = tid; i < NCLS * DCH; i += NTK) s += g_loss[i];
#pragma unroll
        for (int o = 16; o; o >>= 1) s += __shfl_xor_sync(0xffffffffu, s, o);
        if (lane == 0) red[0][wid] = s;
        __syncthreads();
        if (tid == 0) {
            float num = red[0][0] + red[0][1] + red[0][2] + red[0][3];
            float den = 0.f;
#pragma unroll
            for (int c = 0; c < NCLS; c++) den += (g_n[c] >= 1000.0f) ? 1.0f : 0.0f;
            outp[0] = num / den;
            g_ticket = 0u;   // reset for next graph replay
        }
    }
}

extern "C" void kernel_launch(void* const* d_in, const int* in_sizes, int n_in,
                              void* d_out, int out_size) {
    const float* feature;
    const int*   label;
    if (in_sizes[0] == DCH * FPX) {
        feature = (const float*)d_in[0];
        label   = (const int*)d_in[1];
    } else {
        feature = (const float*)d_in[1];
        label   = (const int*)d_in[0];
    }
    count_compact_kernel<<<NCLS, NTA>>>(label);
    klass_kernel<<<dim3(NCLS, DCH), NTK>>>(feature, (float*)d_out);
}

// round 6
// speedup vs baseline: 1.7334x; 1.3566x over previous
#include <cuda_runtime.h>

#define NCLS 19
#define FPX  16384      // 128*128 feature pixels
#define DCH  64
#define LBL  512
#define NTC  256        // count block size
#define NTP  256        // compact block size
#define NTK  256        // klass block size
#define PADQ (4*NTK)    // pad quantum

__device__ unsigned char g_cnt8[NCLS * FPX];   // per-class per-pixel weights (0..16)
__device__ unsigned int  g_pairs[NCLS * FPX];  // (w<<16)|pixel, pixel-ordered, zero-padded
__device__ int           g_len[NCLS];          // padded length
__device__ float         g_n[NCLS];
__device__ float         g_loss[NCLS * DCH];
__device__ unsigned int  g_ticket;

typedef unsigned long long ull;

__device__ __forceinline__ float ex2f(float x) {
    float y; asm("ex2.approx.ftz.f32 %0, %1;" : "=f"(y) : "f"(x)); return y;
}
__device__ __forceinline__ ull pk2(float lo, float hi) {
    ull r; asm("mov.b64 %0, {%1, %2};" : "=l"(r) : "f"(lo), "f"(hi)); return r;
}
__device__ __forceinline__ void upk2(float& lo, float& hi, ull v) {
    asm("mov.b64 {%0, %1}, %2;" : "=f"(lo), "=f"(hi) : "l"(v));
}
__device__ __forceinline__ ull fma2(ull a, ull b, ull c) {
    ull d; asm("fma.rn.f32x2 %0, %1, %2, %3;" : "=l"(d) : "l"(a), "l"(b), "l"(c)); return d;
}
__device__ __forceinline__ ull add2(ull a, ull b) {
    ull d; asm("add.rn.f32x2 %0, %1, %2;" : "=l"(d) : "l"(a), "l"(b)); return d;
}
__device__ __forceinline__ ull mul2(ull a, ull b) {
    ull d; asm("mul.rn.f32x2 %0, %1, %2;" : "=l"(d) : "l"(a), "l"(b)); return d;
}

// K1: per-(pixel, class) 4x4 counts. 64 blocks x 256 threads; each thread owns
// one feature pixel and a private smem column (conflict-free: bank = tid%32).
__global__ __launch_bounds__(NTC) void count_kernel(const int* __restrict__ label) {
    __shared__ int sc[NCLS][NTC];
    const int tid = threadIdx.x;
#pragma unroll
    for (int c = 0; c < NCLS; c++) sc[c][tid] = 0;

    const int fp = blockIdx.x * NTC + tid;
    const int r = fp >> 7, c = fp & 127;
    const int4* lp = reinterpret_cast<const int4*>(label + (r * 4) * LBL + c * 4);
#pragma unroll
    for (int dr = 0; dr < 4; dr++) {
        int4 v = lp[dr * (LBL / 4)];
        sc[v.x][tid]++; sc[v.y][tid]++; sc[v.z][tid]++; sc[v.w][tid]++;
    }
#pragma unroll
    for (int cc = 0; cc < NCLS; cc++)
        g_cnt8[cc * FPX + fp] = (unsigned char)sc[cc][tid];
}

// K2: ordered compaction, one block per class, single block scan.
__global__ __launch_bounds__(NTP) void compact_kernel() {
    const int cls = blockIdx.x;
    const int tid = threadIdx.x, lane = tid & 31, wid = tid >> 5;
    __shared__ unsigned int wtot[8], wbase[8];
    __shared__ int wsumw[8];
    __shared__ unsigned int stot;

    // each thread owns 64 contiguous pixels (16 words)
    unsigned int d[16];
    const uint4* src = reinterpret_cast<const uint4*>(g_cnt8 + cls * FPX) + tid * 4;
#pragma unroll
    for (int j = 0; j < 4; j++) {
        uint4 v = src[j];
        d[j * 4 + 0] = v.x; d[j * 4 + 1] = v.y; d[j * 4 + 2] = v.z; d[j * 4 + 3] = v.w;
    }
    int nnz = 0, ws = 0;
#pragma unroll
    for (int j = 0; j < 16; j++) {
        unsigned u = d[j];
        nnz += __popc(__vcmpne4(u, 0u) & 0x01010101u);
        ws  += (u & 0xff) + ((u >> 8) & 0xff) + ((u >> 16) & 0xff) + (u >> 24);
    }
    unsigned inc = (unsigned)nnz;
#pragma unroll
    for (int o = 1; o < 32; o <<= 1) {
        unsigned t = __shfl_up_sync(0xffffffffu, inc, o);
        if (lane >= o) inc += t;
    }
    if (lane == 31) wtot[wid] = inc;
    int wsr = ws;
#pragma unroll
    for (int o = 16; o; o >>= 1) wsr += __shfl_xor_sync(0xffffffffu, wsr, o);
    if (lane == 0) wsumw[wid] = wsr;
    __syncthreads();
    if (tid == 0) {
        unsigned run = 0; int nsum = 0;
#pragma unroll
        for (int j = 0; j < 8; j++) { wbase[j] = run; run += wtot[j]; nsum += wsumw[j]; }
        stot = run;
        g_n[cls] = (float)nsum;
    }
    __syncthreads();

    unsigned rank = wbase[wid] + inc - (unsigned)nnz;
    unsigned int* __restrict__ out = g_pairs + cls * FPX;
    const int base = tid * 64;
#pragma unroll
    for (int j = 0; j < 16; j++) {
        unsigned u = d[j];
#pragma unroll
        for (int b = 0; b < 4; b++) {
            unsigned w = (u >> (8 * b)) & 0xffu;
            if (w) out[rank++] = (w << 16) | (unsigned)(base + j * 4 + b);
        }
    }
    unsigned total = stot;
    unsigned pl = (total + PADQ - 1) & ~(unsigned)(PADQ - 1);
    for (unsigned k = total + tid; k < pl; k += NTP) out[k] = 0u;
    if (tid == 0) g_len[cls] = (int)pl;
}

// K3: one block per (class, channel). Dense moments + compacted 4-wide KDE.
__global__ __launch_bounds__(NTK) void klass_kernel(const float* __restrict__ feat,
                                                    float* __restrict__ outp) {
    const int cls = blockIdx.x, dd = blockIdx.y;
    const float* __restrict__ fb = feat + dd * FPX;
    const float4* __restrict__ f4 = reinterpret_cast<const float4*>(fb);
    const uchar4* __restrict__ cb = reinterpret_cast<const uchar4*>(g_cnt8 + cls * FPX);
    const unsigned int* __restrict__ pr = g_pairs + cls * FPX;
    const int len = g_len[cls];
    const float n = g_n[cls];
    const int tid = threadIdx.x, lane = tid & 31, wid = tid >> 5;

    __shared__ float red[10][8];
    __shared__ bool  amlast;

    float loss = 0.f;
    if (n >= 1000.0f) {
        // ---- pass 1: dense moments (streaming, coalesced) ----
        float s0 = 0.f, s1 = 0.f, s2 = 0.f;
#pragma unroll 4
        for (int i = tid; i < FPX / 4; i += NTK) {
            float4 fv = f4[i];
            uchar4 wv = cb[i];
            float w0 = (float)wv.x, w1 = (float)wv.y, w2 = (float)wv.z, w3 = (float)wv.w;
            s0 += (w0 + w1) + (w2 + w3);
            s1 = fmaf(w0, fv.x, fmaf(w1, fv.y, fmaf(w2, fv.z, fmaf(w3, fv.w, s1))));
            s2 = fmaf(w0 * fv.x, fv.x, fmaf(w1 * fv.y, fv.y,
                 fmaf(w2 * fv.z, fv.z, fmaf(w3 * fv.w, fv.w, s2))));
        }
#pragma unroll
        for (int o = 16; o; o >>= 1) {
            s0 += __shfl_xor_sync(0xffffffffu, s0, o);
            s1 += __shfl_xor_sync(0xffffffffu, s1, o);
            s2 += __shfl_xor_sync(0xffffffffu, s2, o);
        }
        if (lane == 0) { red[0][wid] = s0; red[1][wid] = s1; red[2][wid] = s2; }
        __syncthreads();
        float S0 = 0.f, S1 = 0.f, S2 = 0.f;
#pragma unroll
        for (int j = 0; j < 8; j++) { S0 += red[0][j]; S1 += red[1][j]; S2 += red[2][j]; }

        float nsafe = fmaxf(S0, 1.0f);
        float miu   = S1 / nsafe;
        float var   = fmaxf(S2 / nsafe - miu * miu, 0.0f) + 1e-10f;
        float inv5  = 5.0f * rsqrtf(var);          // 5/std
        float dini  = 15.0f - miu * inv5;          // d at k=-3: d = u+15

        // ---- pass 2: compacted 4-wide 7-bin KDE ----
        // d_k = u - 5k (start k=-3), arg = C2*d^2 (<=0), d -> d-5
        const float C2 = -0.72134752f;             // -0.5*log2(e)
        const ull inv5_2 = pk2(inv5, inv5);
        const ull dini_2 = pk2(dini, dini);
        const ull C2_2   = pk2(C2, C2);
        const ull m5_2   = pk2(-5.0f, -5.0f);
        ull acc[7];
#pragma unroll
        for (int k = 0; k < 7; k++) acc[k] = 0ull;

        for (int i = tid * 4; i < len; i += NTK * 4) {
            uint4 p = *reinterpret_cast<const uint4*>(pr + i);
            float f0 = fb[p.x & 0xFFFFu];
            float f1 = fb[p.y & 0xFFFFu];
            float f2v = fb[p.z & 0xFFFFu];
            float f3 = fb[p.w & 0xFFFFu];
            ull w01 = pk2((float)(p.x >> 16), (float)(p.y >> 16));
            ull w23 = pk2((float)(p.z >> 16), (float)(p.w >> 16));
            ull dA = fma2(pk2(f0, f1), inv5_2, dini_2);
            ull dB = fma2(pk2(f2v, f3), inv5_2, dini_2);
#pragma unroll
            for (int k = 0; k < 7; k++) {
                ull pA = mul2(dA, C2_2);
                ull aA = mul2(pA, dA);
                ull pB = mul2(dB, C2_2);
                ull aB = mul2(pB, dB);
                float la, ha, lb, hb;
                upk2(la, ha, aA);
                upk2(lb, hb, aB);
                acc[k] = fma2(w01, pk2(ex2f(la), ex2f(ha)), acc[k]);
                acc[k] = fma2(w23, pk2(ex2f(lb), ex2f(hb)), acc[k]);
                if (k < 6) { dA = add2(dA, m5_2); dB = add2(dB, m5_2); }
            }
        }

#pragma unroll
        for (int k = 0; k < 7; k++) {
            float lo, hi; upk2(lo, hi, acc[k]);
            float v = lo + hi;
#pragma unroll
            for (int o = 16; o; o >>= 1) v += __shfl_xor_sync(0xffffffffu, v, o);
            if (lane == 0) red[3 + k][wid] = v;
        }
        __syncthreads();

        if (tid == 0) {
            float s[7], tot = 0.f;
#pragma unroll
            for (int k = 0; k < 7; k++) {
                float v = 0.f;
#pragma unroll
                for (int j = 0; j < 8; j++) v += red[3 + k][j];
                s[k] = v; tot += v;
            }
            float inv = 1.0f / fmaxf(tot, 1e-30f);
            const float targ[7] = {0.00443305f, 0.05400558f, 0.24203623f, 0.39905027f,
                                   0.24203623f, 0.05400558f, 0.00443305f};
            float L = 0.f;
#pragma unroll
            for (int k = 0; k < 7; k++) {
                float dif = fabsf(s[k] * inv - targ[k]);
                L += (dif < 1.0f) ? 0.5f * dif * dif : (dif - 0.5f);
            }
            loss = L * (1.0f / (7.0f * (float)DCH));
        }
    }
    if (tid == 0) g_loss[cls * DCH + dd] = loss;
    __threadfence();
    if (tid == 0) {
        unsigned t = atomicAdd(&g_ticket, 1u);
        amlast = (t == (unsigned)(NCLS * DCH - 1));
    }
    __syncthreads();

    if (amlast) {
        __threadfence();
        float s = 0.f;
        for (int i = tid; i < NCLS * DCH; i += NTK) s += g_loss[i];
#pragma unroll
        for (int o = 16; o; o >>= 1) s += __shfl_xor_sync(0xffffffffu, s, o);
        if (lane == 0) red[0][wid] = s;
        __syncthreads();
        if (tid == 0) {
            float num = 0.f;
#pragma unroll
            for (int j = 0; j < 8; j++) num += red[0][j];
            float den = 0.f;
#pragma unroll
            for (int c = 0; c < NCLS; c++) den += (g_n[c] >= 1000.0f) ? 1.0f : 0.0f;
            outp[0] = num / den;
            g_ticket = 0u;   // reset for next graph replay
        }
    }
}

extern "C" void kernel_launch(void* const* d_in, const int* in_sizes, int n_in,
                              void* d_out, int out_size) {
    const float* feature;
    const int*   label;
    if (in_sizes[0] == DCH * FPX) {
        feature = (const float*)d_in[0];
        label   = (const int*)d_in[1];
    } else {
        feature = (const float*)d_in[1];
        label   = (const int*)d_in[0];
    }
    count_kernel<<<FPX / NTC, NTC>>>(label);
    compact_kernel<<<NCLS, NTP>>>();
    klass_kernel<<<dim3(NCLS, DCH), NTK>>>(feature, (float*)d_out);
}

// round 7
// speedup vs baseline: 1.9286x; 1.1126x over previous
#include <cuda_runtime.h>

#define NCLS 19
#define FPX  16384      // 128*128 feature pixels
#define DCH  64
#define LBL  512
#define NTC  128        // count block size
#define NTP  256        // compact block size
#define NTK  128        // klass block size
#define PADQ (4*NTK)    // pad quantum = 512
#define CHPX 8192       // compact chunk pixels

__device__ unsigned char g_cnt8[NCLS * FPX];   // per-class per-pixel weights (0..16)
__device__ unsigned int  g_pairs[NCLS * FPX];  // (w<<16)|pixel, pixel-ordered, zero-padded
__device__ int           g_len[NCLS];          // padded length
__device__ float         g_n[NCLS];
__device__ float         g_loss[NCLS * DCH];
__device__ unsigned int  g_ticket;

typedef unsigned long long ull;

__device__ __forceinline__ float ex2f(float x) {
    float y; asm("ex2.approx.ftz.f32 %0, %1;" : "=f"(y) : "f"(x)); return y;
}
__device__ __forceinline__ ull pk2(float lo, float hi) {
    ull r; asm("mov.b64 %0, {%1, %2};" : "=l"(r) : "f"(lo), "f"(hi)); return r;
}
__device__ __forceinline__ ull pkb(unsigned lo, unsigned hi) {
    ull r; asm("mov.b64 %0, {%1, %2};" : "=l"(r) : "r"(lo), "r"(hi)); return r;
}
__device__ __forceinline__ void upk2(float& lo, float& hi, ull v) {
    asm("mov.b64 {%0, %1}, %2;" : "=f"(lo), "=f"(hi) : "l"(v));
}
__device__ __forceinline__ ull fma2(ull a, ull b, ull c) {
    ull d; asm("fma.rn.f32x2 %0, %1, %2, %3;" : "=l"(d) : "l"(a), "l"(b), "l"(c)); return d;
}
__device__ __forceinline__ ull mul2(ull a, ull b) {
    ull d; asm("mul.rn.f32x2 %0, %1, %2;" : "=l"(d) : "l"(a), "l"(b)); return d;
}

// constants for the bin recurrence (exponent -12.5(k-t)^2, base-2):
//   G3 = 2^( CL*x^2 + 100 ),  x = 3-|t|          (2^100 scaling cancels in norm)
//   R3 = 2^( 90.16844 - 36.067376*|t| )          ( = exp(62.5-25|t|) )
//   R_{k-1} = R_k * exp(-25)
#define CLK  (-18.033688011112042f)   // -12.5*log2(e)
#define RA   (-36.06737602222409f)    // -25*log2(e)
#define RB   (90.16844005556021f)     //  62.5*log2(e)
#define CCM  (1.3887943864964021e-11f) // exp(-25)

// K1: per-(pixel,class) 4x4 counts, register-only SIMD. 128 blocks x 128 thr.
__global__ __launch_bounds__(NTC) void count_kernel(const int* __restrict__ label) {
    const int fp = blockIdx.x * NTC + threadIdx.x;
    const int r = fp >> 7, c = fp & 127;
    const int4* lp = reinterpret_cast<const int4*>(label + (r * 4) * LBL + c * 4);
    unsigned pk[4];
#pragma unroll
    for (int dr = 0; dr < 4; dr++) {
        int4 v = lp[dr * (LBL / 4)];
        pk[dr] = (unsigned)v.x | ((unsigned)v.y << 8) |
                 ((unsigned)v.z << 16) | ((unsigned)v.w << 24);
    }
#pragma unroll
    for (int cls = 0; cls < NCLS; cls++) {
        unsigned u = (unsigned)cls * 0x01010101u;
        int s = 0;
#pragma unroll
        for (int dr = 0; dr < 4; dr++)
            s = __dp4a((int)(__vcmpeq4(pk[dr], u) & 0x01010101u), 0x01010101, s);
        g_cnt8[cls * FPX + fp] = (unsigned char)s;
    }
}

// K2: ordered compaction with smem staging + coalesced copy-out. 1 block/class.
__global__ __launch_bounds__(NTP) void compact_kernel() {
    const int cls = blockIdx.x;
    const int tid = threadIdx.x, lane = tid & 31, wid = tid >> 5;
    __shared__ unsigned sbuf[CHPX];
    __shared__ unsigned wtot[8], wbase[8];
    __shared__ int wsumw[8];
    __shared__ unsigned chtot_s;
    __shared__ int nacc_s;

    if (tid == 0) nacc_s = 0;
    unsigned gbase = 0;
    unsigned int* __restrict__ out = g_pairs + cls * FPX;

    for (int h = 0; h < FPX / CHPX; h++) {
        const int pxbase = h * CHPX + tid * 32;
        unsigned d[8];
        const uint4* src = reinterpret_cast<const uint4*>(g_cnt8 + cls * FPX + h * CHPX)
                           + tid * 2;
        uint4 v0 = src[0], v1 = src[1];
        d[0]=v0.x; d[1]=v0.y; d[2]=v0.z; d[3]=v0.w;
        d[4]=v1.x; d[5]=v1.y; d[6]=v1.z; d[7]=v1.w;

        int nnz = 0, ws = 0;
#pragma unroll
        for (int j = 0; j < 8; j++) {
            unsigned u = d[j];
            nnz += __popc(__vcmpne4(u, 0u) & 0x01010101u);
            ws  += __dp4a((int)u, 0x01010101, 0);
        }
        unsigned inc = (unsigned)nnz;
#pragma unroll
        for (int o = 1; o < 32; o <<= 1) {
            unsigned t = __shfl_up_sync(0xffffffffu, inc, o);
            if (lane >= o) inc += t;
        }
        if (lane == 31) wtot[wid] = inc;
        int wsr = ws;
#pragma unroll
        for (int o = 16; o; o >>= 1) wsr += __shfl_xor_sync(0xffffffffu, wsr, o);
        if (lane == 0) wsumw[wid] = wsr;
        __syncthreads();
        if (tid == 0) {
            unsigned run = 0; int ns = 0;
#pragma unroll
            for (int j = 0; j < 8; j++) { wbase[j] = run; run += wtot[j]; ns += wsumw[j]; }
            chtot_s = run;
            nacc_s += ns;
        }
        __syncthreads();

        unsigned rank = wbase[wid] + inc - (unsigned)nnz;
#pragma unroll
        for (int j = 0; j < 8; j++) {
            unsigned u = d[j];
#pragma unroll
            for (int b = 0; b < 4; b++) {
                unsigned w = (u >> (8 * b)) & 0xffu;
                if (w) sbuf[rank++] = (w << 16) | (unsigned)(pxbase + j * 4 + b);
            }
        }
        __syncthreads();
        unsigned chtot = chtot_s;
        for (unsigned j = tid; j < chtot; j += NTP) out[gbase + j] = sbuf[j];
        gbase += chtot;
        __syncthreads();
    }
    unsigned pl = (gbase + PADQ - 1) & ~(unsigned)(PADQ - 1);
    for (unsigned k = gbase + tid; k < pl; k += NTP) out[k] = 0u;
    if (tid == 0) { g_len[cls] = (int)pl; g_n[cls] = (float)nacc_s; }
}

// process one packed pair of compacted samples through the 7-bin recurrence
__device__ __forceinline__ void kde_pair(float fa, float fc, unsigned wa, unsigned wb,
                                         float invs, float nmu,
                                         ull* accP, ull* accN, ull cc2) {
    float t0 = fmaf(fa, invs, nmu);
    float t1 = fmaf(fc, invs, nmu);
    float a0 = fabsf(t0), a1 = fabsf(t1);
    float x0 = 3.0f - a0,  x1 = 3.0f - a1;
    float gl = ex2f(fmaf(CLK * x0, x0, 100.0f));
    float gh = ex2f(fmaf(CLK * x1, x1, 100.0f));
    float rl = ex2f(fmaf(RA, a0, RB));
    float rh = ex2f(fmaf(RA, a1, RB));
    unsigned m0 = (unsigned)(__float_as_int(t0) >> 31);   // all-ones if t<0
    unsigned m1 = (unsigned)(__float_as_int(t1) >> 31);
    unsigned w0b = __float_as_uint((float)wa);
    unsigned w1b = __float_as_uint((float)wb);
    ull wp2 = pkb(w0b & ~m0, w1b & ~m1);
    ull wn2 = pkb(w0b &  m0, w1b &  m1);
    ull g = pk2(gl, gh);
    ull r = pk2(rl, rh);
#pragma unroll
    for (int s = 0; s < 7; s++) {
        accP[s] = fma2(wp2, g, accP[s]);
        accN[s] = fma2(wn2, g, accN[s]);
        if (s < 6) { g = mul2(g, r); r = mul2(r, cc2); }
    }
}

// K3: one block per (class, channel). Dense moments + recurrence KDE.
__global__ __launch_bounds__(NTK) void klass_kernel(const float* __restrict__ feat,
                                                    float* __restrict__ outp) {
    const int cls = blockIdx.x, dd = blockIdx.y;
    const float* __restrict__ fb = feat + dd * FPX;
    const float4* __restrict__ f4 = reinterpret_cast<const float4*>(fb);
    const uchar4* __restrict__ cb = reinterpret_cast<const uchar4*>(g_cnt8 + cls * FPX);
    const unsigned int* __restrict__ pr = g_pairs + cls * FPX;
    const int len = g_len[cls];
    const float n = g_n[cls];
    const int tid = threadIdx.x, lane = tid & 31, wid = tid >> 5;

    __shared__ float red[17][4];
    __shared__ bool  amlast;

    float loss = 0.f;
    if (n >= 1000.0f) {
        // ---- pass 1: dense streaming moments ----
        float s0 = 0.f, s1 = 0.f, s2 = 0.f;
#pragma unroll 4
        for (int i = tid; i < FPX / 4; i += NTK) {
            float4 fv = f4[i];
            uchar4 wv = cb[i];
            float w0 = (float)wv.x, w1 = (float)wv.y, w2 = (float)wv.z, w3 = (float)wv.w;
            s0 += (w0 + w1) + (w2 + w3);
            s1 = fmaf(w0, fv.x, fmaf(w1, fv.y, fmaf(w2, fv.z, fmaf(w3, fv.w, s1))));
            s2 = fmaf(w0 * fv.x, fv.x, fmaf(w1 * fv.y, fv.y,
                 fmaf(w2 * fv.z, fv.z, fmaf(w3 * fv.w, fv.w, s2))));
        }
#pragma unroll
        for (int o = 16; o; o >>= 1) {
            s0 += __shfl_xor_sync(0xffffffffu, s0, o);
            s1 += __shfl_xor_sync(0xffffffffu, s1, o);
            s2 += __shfl_xor_sync(0xffffffffu, s2, o);
        }
        if (lane == 0) { red[0][wid] = s0; red[1][wid] = s1; red[2][wid] = s2; }
        __syncthreads();
        float S0 = 0.f, S1 = 0.f, S2 = 0.f;
#pragma unroll
        for (int j = 0; j < 4; j++) { S0 += red[0][j]; S1 += red[1][j]; S2 += red[2][j]; }

        float nsafe = fmaxf(S0, 1.0f);
        float miu   = S1 / nsafe;
        float var   = fmaxf(S2 / nsafe - miu * miu, 0.0f) + 1e-10f;
        float invs  = rsqrtf(var);                 // 1/std
        float nmu   = -miu * invs;

        // ---- pass 2: compacted recurrence KDE ----
        const ull cc2 = pk2(CCM, CCM);
        ull accP[7], accN[7];
#pragma unroll
        for (int s = 0; s < 7; s++) { accP[s] = 0ull; accN[s] = 0ull; }

        for (int i = tid * 4; i < len; i += NTK * 4) {
            uint4 p = *reinterpret_cast<const uint4*>(pr + i);
            float f0 = fb[p.x & 0xFFFFu];
            float f1 = fb[p.y & 0xFFFFu];
            float f2 = fb[p.z & 0xFFFFu];
            float f3 = fb[p.w & 0xFFFFu];
            kde_pair(f0, f1, p.x >> 16, p.y >> 16, invs, nmu, accP, accN, cc2);
            kde_pair(f2, f3, p.z >> 16, p.w >> 16, invs, nmu, accP, accN, cc2);
        }

#pragma unroll
        for (int s = 0; s < 7; s++) {
            float lo, hi, l2, h2;
            upk2(lo, hi, accP[s]);
            upk2(l2, h2, accN[s]);
            float vP = lo + hi, vN = l2 + h2;
#pragma unroll
            for (int o = 16; o; o >>= 1) {
                vP += __shfl_xor_sync(0xffffffffu, vP, o);
                vN += __shfl_xor_sync(0xffffffffu, vN, o);
            }
            if (lane == 0) { red[3 + s][wid] = vP; red[10 + s][wid] = vN; }
        }
        __syncthreads();

        if (tid == 0) {
            float P[7], N[7];
#pragma unroll
            for (int s = 0; s < 7; s++) {
                P[s] = red[3 + s][0] + red[3 + s][1] + red[3 + s][2] + red[3 + s][3];
                N[s] = red[10 + s][0] + red[10 + s][1] + red[10 + s][2] + red[10 + s][3];
            }
            // accP[s] holds bin (3-s) for t>=0 samples; accN[s] holds bin (s-3)
            float sbin[7], tot = 0.f;
#pragma unroll
            for (int ib = 0; ib < 7; ib++) { sbin[ib] = P[6 - ib] + N[ib]; tot += sbin[ib]; }
            float inv = 1.0f / fmaxf(tot, 1e-30f);
            const float targ[7] = {0.00443305f, 0.05400558f, 0.24203623f, 0.39905027f,
                                   0.24203623f, 0.05400558f, 0.00443305f};
            float L = 0.f;
#pragma unroll
            for (int ib = 0; ib < 7; ib++) {
                float dif = fabsf(sbin[ib] * inv - targ[ib]);
                L += (dif < 1.0f) ? 0.5f * dif * dif : (dif - 0.5f);
            }
            loss = L * (1.0f / (7.0f * (float)DCH));
        }
    }
    if (tid == 0) g_loss[cls * DCH + dd] = loss;
    __threadfence();
    if (tid == 0) {
        unsigned t = atomicAdd(&g_ticket, 1u);
        amlast = (t == (unsigned)(NCLS * DCH - 1));
    }
    __syncthreads();

    if (amlast) {
        __threadfence();
        float s = 0.f;
        for (int i = tid; i < NCLS * DCH; i += NTK) s += g_loss[i];
#pragma unroll
        for (int o = 16; o; o >>= 1) s += __shfl_xor_sync(0xffffffffu, s, o);
        if (lane == 0) red[0][wid] = s;
        __syncthreads();
        if (tid == 0) {
            float num = red[0][0] + red[0][1] + red[0][2] + red[0][3];
            float den = 0.f;
#pragma unroll
            for (int c = 0; c < NCLS; c++) den += (g_n[c] >= 1000.0f) ? 1.0f : 0.0f;
            outp[0] = num / den;
            g_ticket = 0u;   // reset for next graph replay
        }
    }
}

extern "C" void kernel_launch(void* const* d_in, const int* in_sizes, int n_in,
                              void* d_out, int out_size) {
    const float* feature;
    const int*   label;
    if (in_sizes[0] == DCH * FPX) {
        feature = (const float*)d_in[0];
        label   = (const int*)d_in[1];
    } else {
        feature = (const float*)d_in[1];
        label   = (const int*)d_in[0];
    }
    count_kernel<<<FPX / NTC, NTC>>>(label);
    compact_kernel<<<NCLS, NTP>>>();
    klass_kernel<<<dim3(NCLS, DCH), NTK>>>(feature, (float*)d_out);
}